// round 13
// baseline (speedup 1.0000x reference)
#include <cuda_runtime.h>
#include <cuda_fp16.h>
#include <math.h>
#include <stdint.h>

// Problem constants
#define Bb 4
#define Tt 2048
#define Cc 1024
#define Hh 16
#define Dd 64
#define FFN 4096
#define ROWS (Bb*Tt)          // 8192

// ---------------- scratch (device globals; no allocation allowed) ----------
__device__ float g_q   [ROWS*Cc];
__device__ float g_k   [ROWS*Cc];
__device__ float g_v   [ROWS*Cc];
__device__ float g_gate[ROWS*Cc];
__device__ float g_beta[ROWS*Hh];

__device__ __half h_xn [ROWS*Cc];
__device__ __half h_ao [ROWS*Cc];
__device__ __half h_g  [ROWS*FFN];
__device__ __half h_u  [ROWS*FFN];
__device__ __half h_qw [Cc*Cc];
__device__ __half h_kw [Cc*Cc];
__device__ __half h_vw [Cc*Cc];
__device__ __half h_gw [Cc*Cc];
__device__ __half h_ow [Cc*Cc];
__device__ __half h_fg [FFN*Cc];
__device__ __half h_fu [FFN*Cc];
__device__ __half h_fd [Cc*FFN];

// ---------------- helpers ----------------
__device__ __forceinline__ float sigmoidf_(float v) { return 1.f / (1.f + __expf(-v)); }

__device__ __forceinline__ uint32_t smem_u32(const void* p) {
    uint32_t a;
    asm("{ .reg .u64 t; cvta.to.shared.u64 t, %1; cvt.u32.u64 %0, t; }" : "=r"(a) : "l"(p));
    return a;
}
__device__ __forceinline__ void cp_async16(uint32_t dst, const void* src) {
    asm volatile("cp.async.cg.shared.global [%0], [%1], 16;" :: "r"(dst), "l"(src) : "memory");
}
__device__ __forceinline__ void cp_commit() {
    asm volatile("cp.async.commit_group;" ::: "memory");
}
__device__ __forceinline__ void mma_fp16(float* d, const uint32_t* a, const uint32_t* b) {
    asm volatile(
        "mma.sync.aligned.m16n8k16.row.col.f32.f16.f16.f32 "
        "{%0,%1,%2,%3}, {%4,%5,%6,%7}, {%8,%9}, {%0,%1,%2,%3};"
        : "+f"(d[0]), "+f"(d[1]), "+f"(d[2]), "+f"(d[3])
        : "r"(a[0]), "r"(a[1]), "r"(a[2]), "r"(a[3]), "r"(b[0]), "r"(b[1]));
}

// ---------------- elementwise converters ----------------
__global__ void __launch_bounds__(256) f2h_kernel(const float* __restrict__ s,
                                                  __half* __restrict__ d, int n) {
    int i = (blockIdx.x * 256 + threadIdx.x) * 4;
    if (i < n) {
        float4 v = *(const float4*)(s + i);
        *(__half2*)(d + i)     = __floats2half2_rn(v.x, v.y);
        *(__half2*)(d + i + 2) = __floats2half2_rn(v.z, v.w);
    }
}

// ---------------- RMSNorm: fp32 in, fp16 out; one block per row ------------
__global__ void __launch_bounds__(256) rmsnorm_kernel(const float* __restrict__ x,
                                                      const float* __restrict__ w,
                                                      __half* __restrict__ y) {
    int row = blockIdx.x;
    const float4* xr = (const float4*)(x + (size_t)row * Cc);
    const float4* wr = (const float4*)w;
    int tid = threadIdx.x;
    float4 v = xr[tid];
    float s = v.x*v.x + v.y*v.y + v.z*v.z + v.w*v.w;
    #pragma unroll
    for (int off = 16; off; off >>= 1) s += __shfl_xor_sync(0xffffffffu, s, off);
    __shared__ float red[8];
    int wid = tid >> 5, lane = tid & 31;
    if (lane == 0) red[wid] = s;
    __syncthreads();
    float tot = 0.f;
    #pragma unroll
    for (int i = 0; i < 8; i++) tot += red[i];
    float inv = rsqrtf(tot * (1.f / Cc) + 1e-6f);
    float4 wv = wr[tid];
    __half2* yr = (__half2*)(y + (size_t)row * Cc);
    yr[tid*2]   = __floats2half2_rn(v.x * inv * wv.x, v.y * inv * wv.y);
    yr[tid*2+1] = __floats2half2_rn(v.z * inv * wv.z, v.w * inv * wv.w);
}

// ---------------- L2 norm over last dim (64); blockIdx.y picks q/k ---------
__global__ void __launch_bounds__(256) l2norm_kernel(float* __restrict__ q,
                                                     float* __restrict__ k) {
    float* p0 = blockIdx.y ? k : q;
    int vec = blockIdx.x * 8 + (threadIdx.x >> 5);
    int lane = threadIdx.x & 31;
    float2* p = (float2*)(p0 + (size_t)vec * Dd) + lane;
    float2 v = *p;
    float s = v.x*v.x + v.y*v.y;
    #pragma unroll
    for (int off = 16; off; off >>= 1) s += __shfl_xor_sync(0xffffffffu, s, off);
    float inv = 1.f / fmaxf(sqrtf(s), 1e-12f);
    v.x *= inv; v.y *= inv;
    *p = v;
}

// ---------------- beta = sigmoid(xn @ beta_w.T + beta_b); xn is fp16 -------
__global__ void __launch_bounds__(512) beta_kernel(const __half* __restrict__ xn,
                                                   const float* __restrict__ bw,
                                                   const float* __restrict__ bb,
                                                   float* __restrict__ beta) {
    int row = blockIdx.x;
    __shared__ float xs[Cc];
    int tid = threadIdx.x;
    __half2 hv = ((const __half2*)(xn + (size_t)row * Cc))[tid];
    float2 f = __half22float2(hv);
    xs[tid*2] = f.x; xs[tid*2+1] = f.y;
    __syncthreads();
    int w = tid >> 5, lane = tid & 31;
    const float* wr = bw + (size_t)w * Cc;
    float s = 0.f;
    #pragma unroll 8
    for (int c = lane; c < Cc; c += 32) s += xs[c] * wr[c];
    #pragma unroll
    for (int off = 16; off; off >>= 1) s += __shfl_xor_sync(0xffffffffu, s, off);
    if (lane == 0) beta[(size_t)row * Hh + w] = sigmoidf_(s + bb[w]);
}

// ---------------- GatedDeltaNet scan: one block/(b,h), 128 threads ---------
// Thread pair (2d, 2d+1) owns state row d split in k-halves. Prefetched
// loads, double-buffered smem (one bar/step), 4-way split accumulators.
// Output fused: ao = half(gate * o).
__global__ void __launch_bounds__(128) scan_kernel(const float* __restrict__ q,
                                                   const float* __restrict__ k,
                                                   const float* __restrict__ v,
                                                   const float* __restrict__ beta,
                                                   const float* __restrict__ gate,
                                                   __half* __restrict__ ao) {
    int b = blockIdx.x >> 4;
    int h = blockIdx.x & 15;
    int tid = threadIdx.x;
    int d  = tid >> 1;
    int hf = tid & 1;
    const size_t base  = ((size_t)b * Tt) * Cc + h * Dd;
    const size_t bbase = (size_t)b * Tt * Hh + h;
    __shared__ float qs[2][Dd], ks[2][Dd];
    float Mr[32];
    #pragma unroll
    for (int c = 0; c < 32; c++) Mr[c] = 0.f;

    // prefetch t = 0
    float pA = (tid < 64) ? q[base + tid] : k[base + (tid - 64)];
    float pV = v[base + d];
    float pG = gate[base + d];
    float pB = beta[bbase];

    for (int t = 0; t < Tt; t++) {
        int buf = t & 1;
        if (tid < 64) qs[buf][tid] = pA; else ks[buf][tid - 64] = pA;
        float vv = pV, bt = pB, gv = pG;
        __syncthreads();

        // prefetch t+1 (consumed next iteration)
        int tn = (t + 1 < Tt) ? (t + 1) : t;
        size_t nb = base + (size_t)tn * Cc;
        pA = (tid < 64) ? q[nb + tid] : k[nb + (tid - 64)];
        pV = v[nb + d];
        pG = gate[nb + d];
        pB = beta[bbase + (size_t)tn * Hh];

        const float* qrow = &qs[buf][hf * 32];
        const float* krow = &ks[buf][hf * 32];
        float o0 = 0.f, o1 = 0.f, o2 = 0.f, o3 = 0.f;
        float a0 = 0.f, a1 = 0.f, a2 = 0.f, a3 = 0.f;
        #pragma unroll
        for (int c = 0; c < 32; c += 4) {
            o0 += Mr[c+0] * qrow[c+0]; a0 += Mr[c+0] * krow[c+0];
            o1 += Mr[c+1] * qrow[c+1]; a1 += Mr[c+1] * krow[c+1];
            o2 += Mr[c+2] * qrow[c+2]; a2 += Mr[c+2] * krow[c+2];
            o3 += Mr[c+3] * qrow[c+3]; a3 += Mr[c+3] * krow[c+3];
        }
        float oacc = (o0 + o1) + (o2 + o3);
        float kacc = (a0 + a1) + (a2 + a3);
        oacc += __shfl_xor_sync(0xffffffffu, oacc, 1);
        kacc += __shfl_xor_sync(0xffffffffu, kacc, 1);
        float coef = bt * (vv - kacc);
        #pragma unroll
        for (int c = 0; c < 32; c++) Mr[c] += coef * krow[c];
        if (hf == 0) ao[base + (size_t)t * Cc + d] = __float2half(gv * oacc);
    }
}

// ============ fp16 mma.sync GEMM (NT): C = epi(A*B^T) (+res) ===============
// R8-proven core: 3-stage cp.async ring, scalar __half2 fragment LDS.
// A: M x K fp16 row-major (optionally A *= A2 elementwise during fill);
// B: N x K fp16 row-major.
// Tile 128x128x32 halves, 256 threads = 8 warps (4m x 2n), warp tile 32x64.
// SMEM rows of 40 halves (80B): conflict-free __half2 fragment loads.
// epi: 0 none, 1 sigmoid, 2 silu
#define HSTRIDE 40
#define HTILE   (128 * HSTRIDE)       // halves per tile = 5120
#define HTILE_B (HTILE * 2)           // 10240 bytes
#define HSTAGE_B (2 * HTILE_B)        // A+B = 20480
#define GEMM_SMEM (3 * HSTAGE_B)      // 61440

template<bool HAS_A2, bool HAS_RES, bool OUT_HALF>
__device__ __forceinline__ void gemm_core(const __half* __restrict__ A,
                                          const __half* __restrict__ A2,
                                          const __half* __restrict__ B,
                                          const float* __restrict__ res,
                                          void* __restrict__ Cout,
                                          int N, int K, int epi) {
    extern __shared__ __half hsm[];
    const uint32_t s0 = smem_u32(hsm);

    const int tid  = threadIdx.x;
    const int wid  = tid >> 5;
    const int lane = tid & 31;
    const int warp_m = wid >> 1;
    const int warp_n = wid & 1;
    const int gid  = lane >> 2;
    const int qid  = lane & 3;

    const int brow = blockIdx.y * 128;
    const int bcol = blockIdx.x * 128;

    const __half* Aptr  = A + (size_t)brow * K;
    const __half* A2ptr = HAS_A2 ? (A2 + (size_t)brow * K) : nullptr;
    const __half* Bptr  = B + (size_t)bcol * K;

    float acc[2][8][4];
    #pragma unroll
    for (int m = 0; m < 2; m++)
        #pragma unroll
        for (int n = 0; n < 8; n++)
            #pragma unroll
            for (int c = 0; c < 4; c++) acc[m][n][c] = 0.f;

    const int nk = K >> 5;

    auto fill = [&](int kb, int st) {
        const uint32_t aB = s0 + st * HSTAGE_B;
        const uint32_t bB = aB + HTILE_B;
        const int koff = kb * 32;
        if (!HAS_A2) {
            #pragma unroll
            for (int i = 0; i < 2; i++) {
                int c = tid + i * 256;            // 512 chunks of 8 halves
                int row = c >> 2, cp = c & 3;
                cp_async16(aB + row * 80 + cp * 16, Aptr + (size_t)row * K + koff + cp * 8);
            }
        } else {
            #pragma unroll
            for (int i = 0; i < 2; i++) {
                int c = tid + i * 256;
                int row = c >> 2, cp = c & 3;
                const __half2* pa = (const __half2*)(Aptr  + (size_t)row * K + koff + cp * 8);
                const __half2* p2 = (const __half2*)(A2ptr + (size_t)row * K + koff + cp * 8);
                __half2 h0 = __hmul2(pa[0], p2[0]);
                __half2 h1 = __hmul2(pa[1], p2[1]);
                __half2 h2 = __hmul2(pa[2], p2[2]);
                __half2 h3 = __hmul2(pa[3], p2[3]);
                uint32_t addr = aB + row * 80 + cp * 16;
                asm volatile("st.shared.v4.b32 [%0], {%1, %2, %3, %4};"
                    :: "r"(addr),
                       "r"(*(uint32_t*)&h0), "r"(*(uint32_t*)&h1),
                       "r"(*(uint32_t*)&h2), "r"(*(uint32_t*)&h3) : "memory");
            }
        }
        #pragma unroll
        for (int i = 0; i < 2; i++) {
            int c = tid + i * 256;
            int row = c >> 2, cp = c & 3;
            cp_async16(bB + row * 80 + cp * 16, Bptr + (size_t)row * K + koff + cp * 8);
        }
        cp_commit();
    };

    fill(0, 0);
    fill(1, 1);

    int cur = 0;
    for (int kb = 0; kb < nk; kb++) {
        if (kb == nk - 1)
            asm volatile("cp.async.wait_group 0;" ::: "memory");
        else
            asm volatile("cp.async.wait_group 1;" ::: "memory");
        __syncthreads();

        const __half* sA = hsm + cur * (HSTAGE_B / 2);
        const __half* sB = sA + HTILE;

        #pragma unroll
        for (int ks = 0; ks < 2; ks++) {
            const int k0 = ks * 16 + qid * 2;
            uint32_t afr[2][4];
            #pragma unroll
            for (int m = 0; m < 2; m++) {
                int r = warp_m * 32 + m * 16 + gid;
                afr[m][0] = *(const uint32_t*)(sA + (r)     * HSTRIDE + k0);
                afr[m][1] = *(const uint32_t*)(sA + (r + 8) * HSTRIDE + k0);
                afr[m][2] = *(const uint32_t*)(sA + (r)     * HSTRIDE + k0 + 8);
                afr[m][3] = *(const uint32_t*)(sA + (r + 8) * HSTRIDE + k0 + 8);
            }
            #pragma unroll
            for (int n = 0; n < 8; n++) {
                int cn = warp_n * 64 + n * 8 + gid;
                uint32_t bfr[2];
                bfr[0] = *(const uint32_t*)(sB + cn * HSTRIDE + k0);
                bfr[1] = *(const uint32_t*)(sB + cn * HSTRIDE + k0 + 8);
                mma_fp16(acc[0][n], afr[0], bfr);
                mma_fp16(acc[1][n], afr[1], bfr);
            }
        }

        if (kb + 2 < nk) {
            __syncthreads();
            fill(kb + 2, (kb + 2) % 3);
        }
        cur = (cur + 1) % 3;
    }

    // ---- epilogue ----
    #pragma unroll
    for (int m = 0; m < 2; m++) {
        const size_t r0 = (size_t)(brow + warp_m * 32 + m * 16 + gid);
        const size_t r1 = r0 + 8;
        #pragma unroll
        for (int n = 0; n < 8; n++) {
            const int col = bcol + warp_n * 64 + n * 8 + qid * 2;
            float v0 = acc[m][n][0], v1 = acc[m][n][1];
            float v2 = acc[m][n][2], v3 = acc[m][n][3];
            if (epi == 1) {
                v0 = sigmoidf_(v0); v1 = sigmoidf_(v1);
                v2 = sigmoidf_(v2); v3 = sigmoidf_(v3);
            } else if (epi == 2) {
                v0 *= sigmoidf_(v0); v1 *= sigmoidf_(v1);
                v2 *= sigmoidf_(v2); v3 *= sigmoidf_(v3);
            }
            if (HAS_RES) {
                float2 ra = *(const float2*)(res + r0 * N + col);
                float2 rb = *(const float2*)(res + r1 * N + col);
                v0 += ra.x; v1 += ra.y; v2 += rb.x; v3 += rb.y;
            }
            if (OUT_HALF) {
                __half* C = (__half*)Cout;
                *(__half2*)(C + r0 * N + col) = __floats2half2_rn(v0, v1);
                *(__half2*)(C + r1 * N + col) = __floats2half2_rn(v2, v3);
            } else {
                float* C = (float*)Cout;
                *(float2*)(C + r0 * N + col) = make_float2(v0, v1);
                *(float2*)(C + r1 * N + col) = make_float2(v2, v3);
            }
        }
    }
}

// q/k/v/gate fused: blockIdx.z selects; z==3 -> sigmoid
__global__ void __launch_bounds__(256) gemm_qkvg(const __half* __restrict__ A,
                                                 const __half* __restrict__ B0,
                                                 const __half* __restrict__ B1,
                                                 const __half* __restrict__ B2,
                                                 const __half* __restrict__ B3,
                                                 float* __restrict__ C0,
                                                 float* __restrict__ C1,
                                                 float* __restrict__ C2,
                                                 float* __restrict__ C3) {
    int z = blockIdx.z;
    const __half* B = (z == 0) ? B0 : (z == 1) ? B1 : (z == 2) ? B2 : B3;
    float*        C = (z == 0) ? C0 : (z == 1) ? C1 : (z == 2) ? C2 : C3;
    gemm_core<false, false, false>(A, nullptr, B, nullptr, C, Cc, Cc, (z == 3) ? 1 : 0);
}

// ffn gate/up fused: z==0 silu->g(half), z==1 plain->u(half)
__global__ void __launch_bounds__(256) gemm_gu(const __half* __restrict__ A,
                                               const __half* __restrict__ Bg,
                                               const __half* __restrict__ Bu,
                                               __half* __restrict__ Cg,
                                               __half* __restrict__ Cu) {
    int z = blockIdx.z;
    gemm_core<false, false, true>(A, nullptr, z ? Bu : Bg, nullptr, z ? Cu : Cg,
                                  FFN, Cc, z ? 0 : 2);
}

// o-proj: plain + residual, fp32 out
__global__ void __launch_bounds__(256) gemm_res(const __half* __restrict__ A,
                                                const __half* __restrict__ B,
                                                const float* __restrict__ res,
                                                float* __restrict__ C,
                                                int N, int K) {
    gemm_core<false, true, false>(A, nullptr, B, res, C, N, K, 0);
}

// down-proj: A = g*u computed in fill, + residual, fp32 out
__global__ void __launch_bounds__(256) gemm_res_a2(const __half* __restrict__ A,
                                                   const __half* __restrict__ A2,
                                                   const __half* __restrict__ B,
                                                   const float* __restrict__ res,
                                                   float* __restrict__ C,
                                                   int N, int K) {
    gemm_core<true, true, false>(A, A2, B, res, C, N, K, 0);
}

// ---------------- launcher ----------------
extern "C" void kernel_launch(void* const* d_in, const int* in_sizes, int n_in,
                              void* d_out, int out_size) {
    const float* x        = (const float*)d_in[0];
    // d_in[1]=cos, d_in[2]=sin  (unused for layer_idx=0)
    const float* norm1_w  = (const float*)d_in[3];
    const float* norm2_w  = (const float*)d_in[4];
    const float* q_w      = (const float*)d_in[5];
    const float* k_w      = (const float*)d_in[6];
    const float* v_w      = (const float*)d_in[7];
    const float* beta_w   = (const float*)d_in[8];
    const float* beta_b   = (const float*)d_in[9];
    const float* gate_w   = (const float*)d_in[10];
    const float* o_w      = (const float*)d_in[11];
    const float* ffn_gate = (const float*)d_in[12];
    const float* ffn_up   = (const float*)d_in[13];
    const float* ffn_down = (const float*)d_in[14];
    float* out = (float*)d_out;

    float *q, *k, *v, *gate, *beta;
    __half *xn16, *ao16, *g16, *u16, *qw16, *kw16, *vw16, *gw16, *ow16, *fg16, *fu16, *fd16;
    cudaGetSymbolAddress((void**)&q,    g_q);
    cudaGetSymbolAddress((void**)&k,    g_k);
    cudaGetSymbolAddress((void**)&v,    g_v);
    cudaGetSymbolAddress((void**)&gate, g_gate);
    cudaGetSymbolAddress((void**)&beta, g_beta);
    cudaGetSymbolAddress((void**)&xn16, h_xn);
    cudaGetSymbolAddress((void**)&ao16, h_ao);
    cudaGetSymbolAddress((void**)&g16,  h_g);
    cudaGetSymbolAddress((void**)&u16,  h_u);
    cudaGetSymbolAddress((void**)&qw16, h_qw);
    cudaGetSymbolAddress((void**)&kw16, h_kw);
    cudaGetSymbolAddress((void**)&vw16, h_vw);
    cudaGetSymbolAddress((void**)&gw16, h_gw);
    cudaGetSymbolAddress((void**)&ow16, h_ow);
    cudaGetSymbolAddress((void**)&fg16, h_fg);
    cudaGetSymbolAddress((void**)&fu16, h_fu);
    cudaGetSymbolAddress((void**)&fd16, h_fd);

    cudaFuncSetAttribute(gemm_qkvg,   cudaFuncAttributeMaxDynamicSharedMemorySize, GEMM_SMEM);
    cudaFuncSetAttribute(gemm_gu,     cudaFuncAttributeMaxDynamicSharedMemorySize, GEMM_SMEM);
    cudaFuncSetAttribute(gemm_res,    cudaFuncAttributeMaxDynamicSharedMemorySize, GEMM_SMEM);
    cudaFuncSetAttribute(gemm_res_a2, cudaFuncAttributeMaxDynamicSharedMemorySize, GEMM_SMEM);

    const int CC2 = Cc * Cc;          // 1M
    const int CF  = FFN * Cc;         // 4M

    // 0. weight conversions fp32 -> fp16
    f2h_kernel<<<CC2/1024, 256>>>(q_w,      qw16, CC2);
    f2h_kernel<<<CC2/1024, 256>>>(k_w,      kw16, CC2);
    f2h_kernel<<<CC2/1024, 256>>>(v_w,      vw16, CC2);
    f2h_kernel<<<CC2/1024, 256>>>(gate_w,   gw16, CC2);
    f2h_kernel<<<CC2/1024, 256>>>(o_w,      ow16, CC2);
    f2h_kernel<<<CF/1024,  256>>>(ffn_gate, fg16, CF);
    f2h_kernel<<<CF/1024,  256>>>(ffn_up,   fu16, CF);
    f2h_kernel<<<CF/1024,  256>>>(ffn_down, fd16, CF);

    dim3 blk(256);
    dim3 grid_qkvg(Cc / 128, ROWS / 128, 4);
    dim3 grid_c(Cc / 128, ROWS / 128);
    dim3 grid_gu(FFN / 128, ROWS / 128, 2);

    // 1. xn1 = rmsnorm(x, norm1_w) -> fp16
    rmsnorm_kernel<<<ROWS, 256>>>(x, norm1_w, xn16);

    // 2. fused q/k/v/gate projections (+ sigmoid on gate)
    gemm_qkvg<<<grid_qkvg, blk, GEMM_SMEM>>>(xn16, qw16, kw16, vw16, gw16, q, k, v, gate);
    beta_kernel<<<ROWS, 512>>>(xn16, beta_w, beta_b, beta);

    // 3. l2 normalize q, k per head (one launch)
    l2norm_kernel<<<dim3((ROWS * Hh) / 8, 2), 256>>>(q, k);

    // 4. sequential delta-rule scan; writes ao = half(gate*o) directly
    scan_kernel<<<Bb * Hh, 128>>>(q, k, v, beta, gate, ao16);

    // 5. x1 = x + ao @ o_w.T -> out
    gemm_res<<<grid_c, blk, GEMM_SMEM>>>(ao16, ow16, x, out, Cc, Cc);

    // 6. xn2 = rmsnorm(x1, norm2_w) -> fp16
    rmsnorm_kernel<<<ROWS, 256>>>(out, norm2_w, xn16);

    // 7. FFN: g = silu(xn2@Wg.T), u = xn2@Wu.T (half); out += (g*u) @ Wd.T
    gemm_gu<<<grid_gu, blk, GEMM_SMEM>>>(xn16, fg16, fu16, g16, u16);
    gemm_res_a2<<<grid_c, blk, GEMM_SMEM>>>(g16, u16, fd16, out, out, Cc, FFN);
}

// round 15
// speedup vs baseline: 1.0671x; 1.0671x over previous
#include <cuda_runtime.h>
#include <cuda_fp16.h>
#include <math.h>
#include <stdint.h>

// Problem constants
#define Bb 4
#define Tt 2048
#define Cc 1024
#define Hh 16
#define Dd 64
#define FFN 4096
#define ROWS (Bb*Tt)          // 8192

// ---------------- scratch (device globals; no allocation allowed) ----------
__device__ float g_q   [ROWS*Cc];
__device__ float g_k   [ROWS*Cc];
__device__ float g_v   [ROWS*Cc];
__device__ float g_gate[ROWS*Cc];
__device__ float g_beta[ROWS*Hh];

__device__ __half h_xn [ROWS*Cc];
__device__ __half h_ao [ROWS*Cc];
__device__ __half h_g  [ROWS*FFN];
__device__ __half h_u  [ROWS*FFN];
__device__ __half h_qw [Cc*Cc];
__device__ __half h_kw [Cc*Cc];
__device__ __half h_vw [Cc*Cc];
__device__ __half h_gw [Cc*Cc];
__device__ __half h_ow [Cc*Cc];
__device__ __half h_fg [FFN*Cc];
__device__ __half h_fu [FFN*Cc];
__device__ __half h_fd [Cc*FFN];

// ---------------- helpers ----------------
__device__ __forceinline__ float sigmoidf_(float v) { return 1.f / (1.f + __expf(-v)); }

__device__ __forceinline__ uint32_t smem_u32(const void* p) {
    uint32_t a;
    asm("{ .reg .u64 t; cvta.to.shared.u64 t, %1; cvt.u32.u64 %0, t; }" : "=r"(a) : "l"(p));
    return a;
}
__device__ __forceinline__ void cp_async16(uint32_t dst, const void* src) {
    asm volatile("cp.async.cg.shared.global [%0], [%1], 16;" :: "r"(dst), "l"(src) : "memory");
}
__device__ __forceinline__ void cp_commit() {
    asm volatile("cp.async.commit_group;" ::: "memory");
}
__device__ __forceinline__ void mma_fp16(float* d, const uint32_t* a, const uint32_t* b) {
    asm volatile(
        "mma.sync.aligned.m16n8k16.row.col.f32.f16.f16.f32 "
        "{%0,%1,%2,%3}, {%4,%5,%6,%7}, {%8,%9}, {%0,%1,%2,%3};"
        : "+f"(d[0]), "+f"(d[1]), "+f"(d[2]), "+f"(d[3])
        : "r"(a[0]), "r"(a[1]), "r"(a[2]), "r"(a[3]), "r"(b[0]), "r"(b[1]));
}

// ---------------- elementwise converters ----------------
__global__ void __launch_bounds__(256) f2h_kernel(const float* __restrict__ s,
                                                  __half* __restrict__ d, int n) {
    int i = (blockIdx.x * 256 + threadIdx.x) * 4;
    if (i < n) {
        float4 v = *(const float4*)(s + i);
        *(__half2*)(d + i)     = __floats2half2_rn(v.x, v.y);
        *(__half2*)(d + i + 2) = __floats2half2_rn(v.z, v.w);
    }
}
// g *= u (half2, in place)
__global__ void __launch_bounds__(256) gu_kernel(__half2* __restrict__ g,
                                                 const __half2* __restrict__ u) {
    int i = blockIdx.x * 256 + threadIdx.x;
    g[i] = __hmul2(g[i], u[i]);
}

// ---------------- RMSNorm: fp32 in, fp16 out; one block per row ------------
__global__ void __launch_bounds__(256) rmsnorm_kernel(const float* __restrict__ x,
                                                      const float* __restrict__ w,
                                                      __half* __restrict__ y) {
    int row = blockIdx.x;
    const float4* xr = (const float4*)(x + (size_t)row * Cc);
    const float4* wr = (const float4*)w;
    int tid = threadIdx.x;
    float4 v = xr[tid];
    float s = v.x*v.x + v.y*v.y + v.z*v.z + v.w*v.w;
    #pragma unroll
    for (int off = 16; off; off >>= 1) s += __shfl_xor_sync(0xffffffffu, s, off);
    __shared__ float red[8];
    int wid = tid >> 5, lane = tid & 31;
    if (lane == 0) red[wid] = s;
    __syncthreads();
    float tot = 0.f;
    #pragma unroll
    for (int i = 0; i < 8; i++) tot += red[i];
    float inv = rsqrtf(tot * (1.f / Cc) + 1e-6f);
    float4 wv = wr[tid];
    __half2* yr = (__half2*)(y + (size_t)row * Cc);
    yr[tid*2]   = __floats2half2_rn(v.x * inv * wv.x, v.y * inv * wv.y);
    yr[tid*2+1] = __floats2half2_rn(v.z * inv * wv.z, v.w * inv * wv.w);
}

// ---------------- L2 norm over last dim (64); blockIdx.y picks q/k ---------
__global__ void __launch_bounds__(256) l2norm_kernel(float* __restrict__ q,
                                                     float* __restrict__ k) {
    float* p0 = blockIdx.y ? k : q;
    int vec = blockIdx.x * 8 + (threadIdx.x >> 5);
    int lane = threadIdx.x & 31;
    float2* p = (float2*)(p0 + (size_t)vec * Dd) + lane;
    float2 v = *p;
    float s = v.x*v.x + v.y*v.y;
    #pragma unroll
    for (int off = 16; off; off >>= 1) s += __shfl_xor_sync(0xffffffffu, s, off);
    float inv = 1.f / fmaxf(sqrtf(s), 1e-12f);
    v.x *= inv; v.y *= inv;
    *p = v;
}

// ---------------- beta = sigmoid(xn @ beta_w.T + beta_b); xn is fp16 -------
__global__ void __launch_bounds__(512) beta_kernel(const __half* __restrict__ xn,
                                                   const float* __restrict__ bw,
                                                   const float* __restrict__ bb,
                                                   float* __restrict__ beta) {
    int row = blockIdx.x;
    __shared__ float xs[Cc];
    int tid = threadIdx.x;
    __half2 hv = ((const __half2*)(xn + (size_t)row * Cc))[tid];
    float2 f = __half22float2(hv);
    xs[tid*2] = f.x; xs[tid*2+1] = f.y;
    __syncthreads();
    int w = tid >> 5, lane = tid & 31;
    const float* wr = bw + (size_t)w * Cc;
    float s = 0.f;
    #pragma unroll 8
    for (int c = lane; c < Cc; c += 32) s += xs[c] * wr[c];
    #pragma unroll
    for (int off = 16; off; off >>= 1) s += __shfl_xor_sync(0xffffffffu, s, off);
    if (lane == 0) beta[(size_t)row * Hh + w] = sigmoidf_(s + bb[w]);
}

// ---------------- GatedDeltaNet scan: one block/(b,h), 128 threads ---------
// Thread pair (2d, 2d+1) owns state row d split in k-halves. Prefetched
// loads, double-buffered smem (one bar/step), 4-way split accumulators.
// Output fused: ao = half(gate * o).
__global__ void __launch_bounds__(128) scan_kernel(const float* __restrict__ q,
                                                   const float* __restrict__ k,
                                                   const float* __restrict__ v,
                                                   const float* __restrict__ beta,
                                                   const float* __restrict__ gate,
                                                   __half* __restrict__ ao) {
    int b = blockIdx.x >> 4;
    int h = blockIdx.x & 15;
    int tid = threadIdx.x;
    int d  = tid >> 1;
    int hf = tid & 1;
    const size_t base  = ((size_t)b * Tt) * Cc + h * Dd;
    const size_t bbase = (size_t)b * Tt * Hh + h;
    __shared__ float qs[2][Dd], ks[2][Dd];
    float Mr[32];
    #pragma unroll
    for (int c = 0; c < 32; c++) Mr[c] = 0.f;

    // prefetch t = 0
    float pA = (tid < 64) ? q[base + tid] : k[base + (tid - 64)];
    float pV = v[base + d];
    float pG = gate[base + d];
    float pB = beta[bbase];

    for (int t = 0; t < Tt; t++) {
        int buf = t & 1;
        if (tid < 64) qs[buf][tid] = pA; else ks[buf][tid - 64] = pA;
        float vv = pV, bt = pB, gv = pG;
        __syncthreads();

        // prefetch t+1 (consumed next iteration)
        int tn = (t + 1 < Tt) ? (t + 1) : t;
        size_t nb = base + (size_t)tn * Cc;
        pA = (tid < 64) ? q[nb + tid] : k[nb + (tid - 64)];
        pV = v[nb + d];
        pG = gate[nb + d];
        pB = beta[bbase + (size_t)tn * Hh];

        const float* qrow = &qs[buf][hf * 32];
        const float* krow = &ks[buf][hf * 32];
        float o0 = 0.f, o1 = 0.f, o2 = 0.f, o3 = 0.f;
        float a0 = 0.f, a1 = 0.f, a2 = 0.f, a3 = 0.f;
        #pragma unroll
        for (int c = 0; c < 32; c += 4) {
            o0 += Mr[c+0] * qrow[c+0]; a0 += Mr[c+0] * krow[c+0];
            o1 += Mr[c+1] * qrow[c+1]; a1 += Mr[c+1] * krow[c+1];
            o2 += Mr[c+2] * qrow[c+2]; a2 += Mr[c+2] * krow[c+2];
            o3 += Mr[c+3] * qrow[c+3]; a3 += Mr[c+3] * krow[c+3];
        }
        float oacc = (o0 + o1) + (o2 + o3);
        float kacc = (a0 + a1) + (a2 + a3);
        oacc += __shfl_xor_sync(0xffffffffu, oacc, 1);
        kacc += __shfl_xor_sync(0xffffffffu, kacc, 1);
        float coef = bt * (vv - kacc);
        #pragma unroll
        for (int c = 0; c < 32; c++) Mr[c] += coef * krow[c];
        if (hf == 0) ao[base + (size_t)t * Cc + d] = __float2half(gv * oacc);
    }
}

// ============ fp16 mma.sync GEMM (NT): C = epi(A*B^T) (+res) ===============
// R8-proven core: 3-stage cp.async ring, scalar __half2 fragment LDS.
// A: M x K fp16 row-major; B: N x K fp16 row-major.
// Tile 128x128x32 halves, 256 threads = 8 warps (4m x 2n), warp tile 32x64.
// SMEM rows of 40 halves (80B): conflict-free __half2 fragment loads.
// epi: 0 none, 1 sigmoid, 2 silu
#define HSTRIDE 40
#define HTILE   (128 * HSTRIDE)       // halves per tile = 5120
#define HTILE_B (HTILE * 2)           // 10240 bytes
#define HSTAGE_B (2 * HTILE_B)        // A+B = 20480
#define GEMM_SMEM (3 * HSTAGE_B)      // 61440

template<bool HAS_RES, bool OUT_HALF>
__device__ __forceinline__ void gemm_core(const __half* __restrict__ A,
                                          const __half* __restrict__ B,
                                          const float* __restrict__ res,
                                          void* __restrict__ Cout,
                                          int N, int K, int epi) {
    extern __shared__ __half hsm[];
    const uint32_t s0 = smem_u32(hsm);

    const int tid  = threadIdx.x;
    const int wid  = tid >> 5;
    const int lane = tid & 31;
    const int warp_m = wid >> 1;
    const int warp_n = wid & 1;
    const int gid  = lane >> 2;
    const int qid  = lane & 3;

    const int brow = blockIdx.y * 128;
    const int bcol = blockIdx.x * 128;

    const __half* Aptr = A + (size_t)brow * K;
    const __half* Bptr = B + (size_t)bcol * K;

    float acc[2][8][4];
    #pragma unroll
    for (int m = 0; m < 2; m++)
        #pragma unroll
        for (int n = 0; n < 8; n++)
            #pragma unroll
            for (int c = 0; c < 4; c++) acc[m][n][c] = 0.f;

    const int nk = K >> 5;

    auto fill = [&](int kb, int st) {
        const uint32_t aB = s0 + st * HSTAGE_B;
        const uint32_t bB = aB + HTILE_B;
        const int koff = kb * 32;
        #pragma unroll
        for (int i = 0; i < 2; i++) {
            int c = tid + i * 256;            // 512 chunks of 8 halves
            int row = c >> 2, cp = c & 3;
            cp_async16(aB + row * 80 + cp * 16, Aptr + (size_t)row * K + koff + cp * 8);
        }
        #pragma unroll
        for (int i = 0; i < 2; i++) {
            int c = tid + i * 256;
            int row = c >> 2, cp = c & 3;
            cp_async16(bB + row * 80 + cp * 16, Bptr + (size_t)row * K + koff + cp * 8);
        }
        cp_commit();
    };

    fill(0, 0);
    fill(1, 1);

    int cur = 0;
    for (int kb = 0; kb < nk; kb++) {
        if (kb == nk - 1)
            asm volatile("cp.async.wait_group 0;" ::: "memory");
        else
            asm volatile("cp.async.wait_group 1;" ::: "memory");
        __syncthreads();

        const __half* sA = hsm + cur * (HSTAGE_B / 2);
        const __half* sB = sA + HTILE;

        #pragma unroll
        for (int ks = 0; ks < 2; ks++) {
            const int k0 = ks * 16 + qid * 2;
            uint32_t afr[2][4];
            #pragma unroll
            for (int m = 0; m < 2; m++) {
                int r = warp_m * 32 + m * 16 + gid;
                afr[m][0] = *(const uint32_t*)(sA + (r)     * HSTRIDE + k0);
                afr[m][1] = *(const uint32_t*)(sA + (r + 8) * HSTRIDE + k0);
                afr[m][2] = *(const uint32_t*)(sA + (r)     * HSTRIDE + k0 + 8);
                afr[m][3] = *(const uint32_t*)(sA + (r + 8) * HSTRIDE + k0 + 8);
            }
            #pragma unroll
            for (int n = 0; n < 8; n++) {
                int cn = warp_n * 64 + n * 8 + gid;
                uint32_t bfr[2];
                bfr[0] = *(const uint32_t*)(sB + cn * HSTRIDE + k0);
                bfr[1] = *(const uint32_t*)(sB + cn * HSTRIDE + k0 + 8);
                mma_fp16(acc[0][n], afr[0], bfr);
                mma_fp16(acc[1][n], afr[1], bfr);
            }
        }

        if (kb + 2 < nk) {
            __syncthreads();
            fill(kb + 2, (kb + 2) % 3);
        }
        cur = (cur + 1) % 3;
    }

    // ---- epilogue ----
    #pragma unroll
    for (int m = 0; m < 2; m++) {
        const size_t r0 = (size_t)(brow + warp_m * 32 + m * 16 + gid);
        const size_t r1 = r0 + 8;
        #pragma unroll
        for (int n = 0; n < 8; n++) {
            const int col = bcol + warp_n * 64 + n * 8 + qid * 2;
            float v0 = acc[m][n][0], v1 = acc[m][n][1];
            float v2 = acc[m][n][2], v3 = acc[m][n][3];
            if (epi == 1) {
                v0 = sigmoidf_(v0); v1 = sigmoidf_(v1);
                v2 = sigmoidf_(v2); v3 = sigmoidf_(v3);
            } else if (epi == 2) {
                v0 *= sigmoidf_(v0); v1 *= sigmoidf_(v1);
                v2 *= sigmoidf_(v2); v3 *= sigmoidf_(v3);
            }
            if (HAS_RES) {
                float2 ra = *(const float2*)(res + r0 * N + col);
                float2 rb = *(const float2*)(res + r1 * N + col);
                v0 += ra.x; v1 += ra.y; v2 += rb.x; v3 += rb.y;
            }
            if (OUT_HALF) {
                __half* C = (__half*)Cout;
                *(__half2*)(C + r0 * N + col) = __floats2half2_rn(v0, v1);
                *(__half2*)(C + r1 * N + col) = __floats2half2_rn(v2, v3);
            } else {
                float* C = (float*)Cout;
                *(float2*)(C + r0 * N + col) = make_float2(v0, v1);
                *(float2*)(C + r1 * N + col) = make_float2(v2, v3);
            }
        }
    }
}

// q/k/v/gate fused: blockIdx.z selects; z==3 -> sigmoid
__global__ void __launch_bounds__(256) gemm_qkvg(const __half* __restrict__ A,
                                                 const __half* __restrict__ B0,
                                                 const __half* __restrict__ B1,
                                                 const __half* __restrict__ B2,
                                                 const __half* __restrict__ B3,
                                                 float* __restrict__ C0,
                                                 float* __restrict__ C1,
                                                 float* __restrict__ C2,
                                                 float* __restrict__ C3) {
    int z = blockIdx.z;
    const __half* B = (z == 0) ? B0 : (z == 1) ? B1 : (z == 2) ? B2 : B3;
    float*        C = (z == 0) ? C0 : (z == 1) ? C1 : (z == 2) ? C2 : C3;
    gemm_core<false, false>(A, B, nullptr, C, Cc, Cc, (z == 3) ? 1 : 0);
}

// ffn gate/up fused: z==0 silu->g(half), z==1 plain->u(half)
__global__ void __launch_bounds__(256) gemm_gu(const __half* __restrict__ A,
                                               const __half* __restrict__ Bg,
                                               const __half* __restrict__ Bu,
                                               __half* __restrict__ Cg,
                                               __half* __restrict__ Cu) {
    int z = blockIdx.z;
    gemm_core<false, true>(A, z ? Bu : Bg, nullptr, z ? Cu : Cg, FFN, Cc, z ? 0 : 2);
}

// plain + residual, fp32 out (o-proj, down-proj)
__global__ void __launch_bounds__(256) gemm_res(const __half* __restrict__ A,
                                                const __half* __restrict__ B,
                                                const float* __restrict__ res,
                                                float* __restrict__ C,
                                                int N, int K) {
    gemm_core<true, false>(A, B, res, C, N, K, 0);
}

// ---------------- launcher ----------------
extern "C" void kernel_launch(void* const* d_in, const int* in_sizes, int n_in,
                              void* d_out, int out_size) {
    const float* x        = (const float*)d_in[0];
    // d_in[1]=cos, d_in[2]=sin  (unused for layer_idx=0)
    const float* norm1_w  = (const float*)d_in[3];
    const float* norm2_w  = (const float*)d_in[4];
    const float* q_w      = (const float*)d_in[5];
    const float* k_w      = (const float*)d_in[6];
    const float* v_w      = (const float*)d_in[7];
    const float* beta_w   = (const float*)d_in[8];
    const float* beta_b   = (const float*)d_in[9];
    const float* gate_w   = (const float*)d_in[10];
    const float* o_w      = (const float*)d_in[11];
    const float* ffn_gate = (const float*)d_in[12];
    const float* ffn_up   = (const float*)d_in[13];
    const float* ffn_down = (const float*)d_in[14];
    float* out = (float*)d_out;

    float *q, *k, *v, *gate, *beta;
    __half *xn16, *ao16, *g16, *u16, *qw16, *kw16, *vw16, *gw16, *ow16, *fg16, *fu16, *fd16;
    cudaGetSymbolAddress((void**)&q,    g_q);
    cudaGetSymbolAddress((void**)&k,    g_k);
    cudaGetSymbolAddress((void**)&v,    g_v);
    cudaGetSymbolAddress((void**)&gate, g_gate);
    cudaGetSymbolAddress((void**)&beta, g_beta);
    cudaGetSymbolAddress((void**)&xn16, h_xn);
    cudaGetSymbolAddress((void**)&ao16, h_ao);
    cudaGetSymbolAddress((void**)&g16,  h_g);
    cudaGetSymbolAddress((void**)&u16,  h_u);
    cudaGetSymbolAddress((void**)&qw16, h_qw);
    cudaGetSymbolAddress((void**)&kw16, h_kw);
    cudaGetSymbolAddress((void**)&vw16, h_vw);
    cudaGetSymbolAddress((void**)&gw16, h_gw);
    cudaGetSymbolAddress((void**)&ow16, h_ow);
    cudaGetSymbolAddress((void**)&fg16, h_fg);
    cudaGetSymbolAddress((void**)&fu16, h_fu);
    cudaGetSymbolAddress((void**)&fd16, h_fd);

    cudaFuncSetAttribute(gemm_qkvg, cudaFuncAttributeMaxDynamicSharedMemorySize, GEMM_SMEM);
    cudaFuncSetAttribute(gemm_gu,   cudaFuncAttributeMaxDynamicSharedMemorySize, GEMM_SMEM);
    cudaFuncSetAttribute(gemm_res,  cudaFuncAttributeMaxDynamicSharedMemorySize, GEMM_SMEM);

    const int CC2 = Cc * Cc;          // 1M
    const int CF  = FFN * Cc;         // 4M

    // 0. weight conversions fp32 -> fp16
    f2h_kernel<<<CC2/1024, 256>>>(q_w,      qw16, CC2);
    f2h_kernel<<<CC2/1024, 256>>>(k_w,      kw16, CC2);
    f2h_kernel<<<CC2/1024, 256>>>(v_w,      vw16, CC2);
    f2h_kernel<<<CC2/1024, 256>>>(gate_w,   gw16, CC2);
    f2h_kernel<<<CC2/1024, 256>>>(o_w,      ow16, CC2);
    f2h_kernel<<<CF/1024,  256>>>(ffn_gate, fg16, CF);
    f2h_kernel<<<CF/1024,  256>>>(ffn_up,   fu16, CF);
    f2h_kernel<<<CF/1024,  256>>>(ffn_down, fd16, CF);

    dim3 blk(256);
    dim3 grid_qkvg(Cc / 128, ROWS / 128, 4);
    dim3 grid_c(Cc / 128, ROWS / 128);
    dim3 grid_gu(FFN / 128, ROWS / 128, 2);

    // 1. xn1 = rmsnorm(x, norm1_w) -> fp16
    rmsnorm_kernel<<<ROWS, 256>>>(x, norm1_w, xn16);

    // 2. fused q/k/v/gate projections (+ sigmoid on gate)
    gemm_qkvg<<<grid_qkvg, blk, GEMM_SMEM>>>(xn16, qw16, kw16, vw16, gw16, q, k, v, gate);
    beta_kernel<<<ROWS, 512>>>(xn16, beta_w, beta_b, beta);

    // 3. l2 normalize q, k per head (one launch)
    l2norm_kernel<<<dim3((ROWS * Hh) / 8, 2), 256>>>(q, k);

    // 4. sequential delta-rule scan; writes ao = half(gate*o) directly
    scan_kernel<<<Bb * Hh, 128>>>(q, k, v, beta, gate, ao16);

    // 5. x1 = x + ao @ o_w.T -> out
    gemm_res<<<grid_c, blk, GEMM_SMEM>>>(ao16, ow16, x, out, Cc, Cc);

    // 6. xn2 = rmsnorm(x1, norm2_w) -> fp16
    rmsnorm_kernel<<<ROWS, 256>>>(out, norm2_w, xn16);

    // 7. FFN: g = silu(xn2@Wg.T), u = xn2@Wu.T (half); g *= u; out += g @ Wd.T
    gemm_gu<<<grid_gu, blk, GEMM_SMEM>>>(xn16, fg16, fu16, g16, u16);
    gu_kernel<<<(ROWS * FFN) / 512, 256>>>((__half2*)g16, (const __half2*)u16);
    gemm_res<<<grid_c, blk, GEMM_SMEM>>>(g16, fd16, out, out, Cc, FFN);
}

// round 16
// speedup vs baseline: 1.2430x; 1.1649x over previous
#include <cuda_runtime.h>
#include <cuda_fp16.h>
#include <math.h>
#include <stdint.h>

// Problem constants
#define Bb 4
#define Tt 2048
#define Cc 1024
#define Hh 16
#define Dd 64
#define FFN 4096
#define ROWS (Bb*Tt)          // 8192

// ---------------- scratch (device globals; no allocation allowed) ----------
__device__ float g_q   [ROWS*Cc];
__device__ float g_k   [ROWS*Cc];
__device__ float g_v   [ROWS*Cc];
__device__ float g_gate[ROWS*Cc];
__device__ float g_beta[ROWS*Hh];

__device__ __half h_xn [ROWS*Cc];
__device__ __half h_ao [ROWS*Cc];
__device__ __half h_g  [ROWS*FFN];
__device__ __half h_u  [ROWS*FFN];
__device__ __half h_qw [Cc*Cc];
__device__ __half h_kw [Cc*Cc];
__device__ __half h_vw [Cc*Cc];
__device__ __half h_gw [Cc*Cc];
__device__ __half h_ow [Cc*Cc];
__device__ __half h_fg [FFN*Cc];
__device__ __half h_fu [FFN*Cc];
__device__ __half h_fd [Cc*FFN];

// ---------------- helpers ----------------
__device__ __forceinline__ float sigmoidf_(float v) { return 1.f / (1.f + __expf(-v)); }

__device__ __forceinline__ uint32_t smem_u32(const void* p) {
    uint32_t a;
    asm("{ .reg .u64 t; cvta.to.shared.u64 t, %1; cvt.u32.u64 %0, t; }" : "=r"(a) : "l"(p));
    return a;
}
__device__ __forceinline__ void cp_async16(uint32_t dst, const void* src) {
    asm volatile("cp.async.cg.shared.global [%0], [%1], 16;" :: "r"(dst), "l"(src) : "memory");
}
__device__ __forceinline__ void cp_async4(uint32_t dst, const void* src) {
    asm volatile("cp.async.ca.shared.global [%0], [%1], 4;" :: "r"(dst), "l"(src) : "memory");
}
__device__ __forceinline__ void cp_commit() {
    asm volatile("cp.async.commit_group;" ::: "memory");
}
__device__ __forceinline__ void ldmx4(uint32_t* r, uint32_t addr) {
    asm volatile("ldmatrix.sync.aligned.m8n8.x4.shared.b16 {%0,%1,%2,%3}, [%4];"
        : "=r"(r[0]), "=r"(r[1]), "=r"(r[2]), "=r"(r[3]) : "r"(addr));
}
__device__ __forceinline__ void mma_fp16(float* d, const uint32_t* a, const uint32_t* b) {
    asm volatile(
        "mma.sync.aligned.m16n8k16.row.col.f32.f16.f16.f32 "
        "{%0,%1,%2,%3}, {%4,%5,%6,%7}, {%8,%9}, {%0,%1,%2,%3};"
        : "+f"(d[0]), "+f"(d[1]), "+f"(d[2]), "+f"(d[3])
        : "r"(a[0]), "r"(a[1]), "r"(a[2]), "r"(a[3]), "r"(b[0]), "r"(b[1]));
}

// ---------------- elementwise converters ----------------
__global__ void __launch_bounds__(256) f2h_kernel(const float* __restrict__ s,
                                                  __half* __restrict__ d, int n) {
    int i = (blockIdx.x * 256 + threadIdx.x) * 4;
    if (i < n) {
        float4 v = *(const float4*)(s + i);
        *(__half2*)(d + i)     = __floats2half2_rn(v.x, v.y);
        *(__half2*)(d + i + 2) = __floats2half2_rn(v.z, v.w);
    }
}
// g *= u (half2, in place)
__global__ void __launch_bounds__(256) gu_kernel(__half2* __restrict__ g,
                                                 const __half2* __restrict__ u) {
    int i = blockIdx.x * 256 + threadIdx.x;
    g[i] = __hmul2(g[i], u[i]);
}

// ---------------- RMSNorm: fp32 in, fp16 out; one block per row ------------
__global__ void __launch_bounds__(256) rmsnorm_kernel(const float* __restrict__ x,
                                                      const float* __restrict__ w,
                                                      __half* __restrict__ y) {
    int row = blockIdx.x;
    const float4* xr = (const float4*)(x + (size_t)row * Cc);
    const float4* wr = (const float4*)w;
    int tid = threadIdx.x;
    float4 v = xr[tid];
    float s = v.x*v.x + v.y*v.y + v.z*v.z + v.w*v.w;
    #pragma unroll
    for (int off = 16; off; off >>= 1) s += __shfl_xor_sync(0xffffffffu, s, off);
    __shared__ float red[8];
    int wid = tid >> 5, lane = tid & 31;
    if (lane == 0) red[wid] = s;
    __syncthreads();
    float tot = 0.f;
    #pragma unroll
    for (int i = 0; i < 8; i++) tot += red[i];
    float inv = rsqrtf(tot * (1.f / Cc) + 1e-6f);
    float4 wv = wr[tid];
    __half2* yr = (__half2*)(y + (size_t)row * Cc);
    yr[tid*2]   = __floats2half2_rn(v.x * inv * wv.x, v.y * inv * wv.y);
    yr[tid*2+1] = __floats2half2_rn(v.z * inv * wv.z, v.w * inv * wv.w);
}

// ---------------- L2 norm over last dim (64); blockIdx.y picks q/k ---------
__global__ void __launch_bounds__(256) l2norm_kernel(float* __restrict__ q,
                                                     float* __restrict__ k) {
    float* p0 = blockIdx.y ? k : q;
    int vec = blockIdx.x * 8 + (threadIdx.x >> 5);
    int lane = threadIdx.x & 31;
    float2* p = (float2*)(p0 + (size_t)vec * Dd) + lane;
    float2 v = *p;
    float s = v.x*v.x + v.y*v.y;
    #pragma unroll
    for (int off = 16; off; off >>= 1) s += __shfl_xor_sync(0xffffffffu, s, off);
    float inv = 1.f / fmaxf(sqrtf(s), 1e-12f);
    v.x *= inv; v.y *= inv;
    *p = v;
}

// ---------------- beta = sigmoid(xn @ beta_w.T + beta_b); xn is fp16 -------
__global__ void __launch_bounds__(512) beta_kernel(const __half* __restrict__ xn,
                                                   const float* __restrict__ bw,
                                                   const float* __restrict__ bb,
                                                   float* __restrict__ beta) {
    int row = blockIdx.x;
    __shared__ float xs[Cc];
    int tid = threadIdx.x;
    __half2 hv = ((const __half2*)(xn + (size_t)row * Cc))[tid];
    float2 f = __half22float2(hv);
    xs[tid*2] = f.x; xs[tid*2+1] = f.y;
    __syncthreads();
    int w = tid >> 5, lane = tid & 31;
    const float* wr = bw + (size_t)w * Cc;
    float s = 0.f;
    #pragma unroll 8
    for (int c = lane; c < Cc; c += 32) s += xs[c] * wr[c];
    #pragma unroll
    for (int off = 16; off; off >>= 1) s += __shfl_xor_sync(0xffffffffu, s, off);
    if (lane == 0) beta[(size_t)row * Hh + w] = sigmoidf_(s + bb[w]);
}

// ---------------- GatedDeltaNet scan: chunked cp.async staging -------------
// One block per (b,h), 128 threads; thread pair (2d,2d+1) owns state row d
// split in k-halves. TCH timesteps of q/k/v/gate/beta are staged into
// double-buffered SMEM with cp.async; chunk c+1 loads overlap chunk c
// compute, making the loop compute-bound. Output fused: ao = half(gate*o).
#define TCH 16
__global__ void __launch_bounds__(128) scan_kernel(const float* __restrict__ q,
                                                   const float* __restrict__ k,
                                                   const float* __restrict__ v,
                                                   const float* __restrict__ beta,
                                                   const float* __restrict__ gate,
                                                   __half* __restrict__ ao) {
    int b = blockIdx.x >> 4;
    int h = blockIdx.x & 15;
    int tid = threadIdx.x;
    int d  = tid >> 1;
    int hf = tid & 1;
    const size_t base  = ((size_t)b * Tt) * Cc + h * Dd;
    const size_t bbase = (size_t)b * Tt * Hh + h;

    __shared__ float qc[2][TCH][Dd], kc[2][TCH][Dd], vc[2][TCH][Dd], gc[2][TCH][Dd];
    __shared__ float bc[2][TCH];

    float Mr[32];
    #pragma unroll
    for (int c = 0; c < 32; c++) Mr[c] = 0.f;

    auto fill = [&](int c0, int st) {
        const int t0 = c0 * TCH;
        #pragma unroll
        for (int i = 0; i < 8; i++) {
            int id   = tid + i * 128;        // 0..1023 16B-chunks
            int arr  = id >> 8;              // 0..3
            int rem  = id & 255;
            int step = rem >> 4;             // 0..15
            int quad = rem & 15;             // 0..15 (16B each = 4 floats)
            size_t src = base + (size_t)(t0 + step) * Cc + quad * 4;
            float* dst;
            const float* s;
            if (arr == 0)      { s = q    + src; dst = &qc[st][step][quad*4]; }
            else if (arr == 1) { s = k    + src; dst = &kc[st][step][quad*4]; }
            else if (arr == 2) { s = v    + src; dst = &vc[st][step][quad*4]; }
            else               { s = gate + src; dst = &gc[st][step][quad*4]; }
            cp_async16(smem_u32(dst), s);
        }
        if (tid < TCH)
            cp_async4(smem_u32(&bc[st][tid]), beta + bbase + (size_t)(t0 + tid) * Hh);
        cp_commit();
    };

    const int nchunk = Tt / TCH;
    fill(0, 0);

    for (int c = 0; c < nchunk; c++) {
        int st = c & 1;
        if (c + 1 < nchunk) {
            fill(c + 1, st ^ 1);
            asm volatile("cp.async.wait_group 1;" ::: "memory");
        } else {
            asm volatile("cp.async.wait_group 0;" ::: "memory");
        }
        __syncthreads();

        const size_t obase = base + (size_t)(c * TCH) * Cc + d;
        #pragma unroll 2
        for (int tt = 0; tt < TCH; tt++) {
            const float* qrow = &qc[st][tt][hf * 32];
            const float* krow = &kc[st][tt][hf * 32];
            float vv = vc[st][tt][d];
            float gv = gc[st][tt][d];
            float bt = bc[st][tt];
            float o0 = 0.f, o1 = 0.f, o2 = 0.f, o3 = 0.f;
            float a0 = 0.f, a1 = 0.f, a2 = 0.f, a3 = 0.f;
            #pragma unroll
            for (int cc = 0; cc < 32; cc += 4) {
                o0 += Mr[cc+0] * qrow[cc+0]; a0 += Mr[cc+0] * krow[cc+0];
                o1 += Mr[cc+1] * qrow[cc+1]; a1 += Mr[cc+1] * krow[cc+1];
                o2 += Mr[cc+2] * qrow[cc+2]; a2 += Mr[cc+2] * krow[cc+2];
                o3 += Mr[cc+3] * qrow[cc+3]; a3 += Mr[cc+3] * krow[cc+3];
            }
            float oacc = (o0 + o1) + (o2 + o3);
            float kacc = (a0 + a1) + (a2 + a3);
            oacc += __shfl_xor_sync(0xffffffffu, oacc, 1);
            kacc += __shfl_xor_sync(0xffffffffu, kacc, 1);
            float coef = bt * (vv - kacc);
            #pragma unroll
            for (int cc = 0; cc < 32; cc++) Mr[cc] += coef * krow[cc];
            if (hf == 0) ao[obase + (size_t)tt * Cc] = __float2half(gv * oacc);
        }
        __syncthreads();
    }
}

// ============ fp16 mma.sync GEMM (NT) with ldmatrix: C = epi(A*B^T) (+res) =
// R9-measured core (−40us vs scalar LDS under identical scan).
// Tile 128x128x32 halves, 256 threads = 8 warps (4m x 2n), warp tile 32x64.
// SMEM rows of 40 halves (80B): conflict-free ldmatrix.x4.
// 4-stage cp.async ring, one __syncthreads per K-tile.
// epi: 0 none, 1 sigmoid, 2 silu
#define HSTRIDE 40
#define HTILE   (128 * HSTRIDE)       // halves per tile = 5120
#define HTILE_B (HTILE * 2)           // 10240 bytes
#define HSTAGE_B (2 * HTILE_B)        // A+B = 20480
#define NSTAGE  4
#define GEMM_SMEM (NSTAGE * HSTAGE_B) // 81920

template<bool HAS_RES, bool OUT_HALF>
__device__ __forceinline__ void gemm_core(const __half* __restrict__ A,
                                          const __half* __restrict__ B,
                                          const float* __restrict__ res,
                                          void* __restrict__ Cout,
                                          int N, int K, int epi) {
    extern __shared__ __half hsm[];
    const uint32_t s0 = smem_u32(hsm);

    const int tid  = threadIdx.x;
    const int wid  = tid >> 5;
    const int lane = tid & 31;
    const int warp_m = wid >> 1;
    const int warp_n = wid & 1;
    const int gid  = lane >> 2;
    const int qid  = lane & 3;

    const int brow = blockIdx.y * 128;
    const int bcol = blockIdx.x * 128;

    const __half* Aptr = A + (size_t)brow * K;
    const __half* Bptr = B + (size_t)bcol * K;

    // ldmatrix lane address offsets (bytes) within a stage
    const uint32_t aOff = ((warp_m * 32 + (lane & 15)) * HSTRIDE + ((lane >> 4) * 8)) * 2;
    const uint32_t bOff = ((warp_n * 64 + ((lane & 7) | ((lane >> 4) << 3))) * HSTRIDE
                          + (((lane >> 3) & 1) * 8)) * 2;

    float acc[2][8][4];
    #pragma unroll
    for (int m = 0; m < 2; m++)
        #pragma unroll
        for (int n = 0; n < 8; n++)
            #pragma unroll
            for (int c = 0; c < 4; c++) acc[m][n][c] = 0.f;

    const int nk = K >> 5;

    auto fill = [&](int kb, int st) {
        const uint32_t aB = s0 + st * HSTAGE_B;
        const uint32_t bB = aB + HTILE_B;
        const int koff = kb * 32;
        #pragma unroll
        for (int i = 0; i < 2; i++) {
            int c = tid + i * 256;            // 512 chunks of 8 halves
            int row = c >> 2, cp = c & 3;
            cp_async16(aB + row * 80 + cp * 16, Aptr + (size_t)row * K + koff + cp * 8);
        }
        #pragma unroll
        for (int i = 0; i < 2; i++) {
            int c = tid + i * 256;
            int row = c >> 2, cp = c & 3;
            cp_async16(bB + row * 80 + cp * 16, Bptr + (size_t)row * K + koff + cp * 8);
        }
        cp_commit();
    };

    fill(0, 0); fill(1, 1); fill(2, 2);

    int cur = 0;
    for (int kb = 0; kb < nk; kb++) {
        if (kb + 2 < nk)
            asm volatile("cp.async.wait_group 2;" ::: "memory");
        else if (kb + 1 < nk)
            asm volatile("cp.async.wait_group 1;" ::: "memory");
        else
            asm volatile("cp.async.wait_group 0;" ::: "memory");
        __syncthreads();

        if (kb + 3 < nk) fill(kb + 3, (kb + 3) & 3);

        const uint32_t sAu = s0 + cur * HSTAGE_B;
        const uint32_t sBu = sAu + HTILE_B;

        #pragma unroll
        for (int ks = 0; ks < 2; ks++) {
            const uint32_t kadd = ks * 32;      // 16 halves = 32 bytes
            uint32_t a0[4], a1[4], bf[4][4];
            ldmx4(a0, sAu + aOff + kadd);
            ldmx4(a1, sAu + aOff + kadd + 16 * HSTRIDE * 2);
            #pragma unroll
            for (int p = 0; p < 4; p++)
                ldmx4(bf[p], sBu + bOff + kadd + p * 16 * HSTRIDE * 2);
            #pragma unroll
            for (int n = 0; n < 8; n++) {
                const uint32_t* bp = &bf[n >> 1][(n & 1) * 2];
                mma_fp16(acc[0][n], a0, bp);
                mma_fp16(acc[1][n], a1, bp);
            }
        }
        cur = (cur + 1) & 3;
    }

    // ---- epilogue ----
    #pragma unroll
    for (int m = 0; m < 2; m++) {
        const size_t r0 = (size_t)(brow + warp_m * 32 + m * 16 + gid);
        const size_t r1 = r0 + 8;
        #pragma unroll
        for (int n = 0; n < 8; n++) {
            const int col = bcol + warp_n * 64 + n * 8 + qid * 2;
            float v0 = acc[m][n][0], v1 = acc[m][n][1];
            float v2 = acc[m][n][2], v3 = acc[m][n][3];
            if (epi == 1) {
                v0 = sigmoidf_(v0); v1 = sigmoidf_(v1);
                v2 = sigmoidf_(v2); v3 = sigmoidf_(v3);
            } else if (epi == 2) {
                v0 *= sigmoidf_(v0); v1 *= sigmoidf_(v1);
                v2 *= sigmoidf_(v2); v3 *= sigmoidf_(v3);
            }
            if (HAS_RES) {
                float2 ra = *(const float2*)(res + r0 * N + col);
                float2 rb = *(const float2*)(res + r1 * N + col);
                v0 += ra.x; v1 += ra.y; v2 += rb.x; v3 += rb.y;
            }
            if (OUT_HALF) {
                __half* C = (__half*)Cout;
                *(__half2*)(C + r0 * N + col) = __floats2half2_rn(v0, v1);
                *(__half2*)(C + r1 * N + col) = __floats2half2_rn(v2, v3);
            } else {
                float* C = (float*)Cout;
                *(float2*)(C + r0 * N + col) = make_float2(v0, v1);
                *(float2*)(C + r1 * N + col) = make_float2(v2, v3);
            }
        }
    }
}

// q/k/v/gate fused: blockIdx.z selects; z==3 -> sigmoid
__global__ void __launch_bounds__(256) gemm_qkvg(const __half* __restrict__ A,
                                                 const __half* __restrict__ B0,
                                                 const __half* __restrict__ B1,
                                                 const __half* __restrict__ B2,
                                                 const __half* __restrict__ B3,
                                                 float* __restrict__ C0,
                                                 float* __restrict__ C1,
                                                 float* __restrict__ C2,
                                                 float* __restrict__ C3) {
    int z = blockIdx.z;
    const __half* B = (z == 0) ? B0 : (z == 1) ? B1 : (z == 2) ? B2 : B3;
    float*        C = (z == 0) ? C0 : (z == 1) ? C1 : (z == 2) ? C2 : C3;
    gemm_core<false, false>(A, B, nullptr, C, Cc, Cc, (z == 3) ? 1 : 0);
}

// ffn gate/up fused: z==0 silu->g(half), z==1 plain->u(half)
__global__ void __launch_bounds__(256) gemm_gu(const __half* __restrict__ A,
                                               const __half* __restrict__ Bg,
                                               const __half* __restrict__ Bu,
                                               __half* __restrict__ Cg,
                                               __half* __restrict__ Cu) {
    int z = blockIdx.z;
    gemm_core<false, true>(A, z ? Bu : Bg, nullptr, z ? Cu : Cg, FFN, Cc, z ? 0 : 2);
}

// plain + residual, fp32 out (o-proj, down-proj)
__global__ void __launch_bounds__(256) gemm_res(const __half* __restrict__ A,
                                                const __half* __restrict__ B,
                                                const float* __restrict__ res,
                                                float* __restrict__ C,
                                                int N, int K) {
    gemm_core<true, false>(A, B, res, C, N, K, 0);
}

// ---------------- launcher ----------------
extern "C" void kernel_launch(void* const* d_in, const int* in_sizes, int n_in,
                              void* d_out, int out_size) {
    const float* x        = (const float*)d_in[0];
    // d_in[1]=cos, d_in[2]=sin  (unused for layer_idx=0)
    const float* norm1_w  = (const float*)d_in[3];
    const float* norm2_w  = (const float*)d_in[4];
    const float* q_w      = (const float*)d_in[5];
    const float* k_w      = (const float*)d_in[6];
    const float* v_w      = (const float*)d_in[7];
    const float* beta_w   = (const float*)d_in[8];
    const float* beta_b   = (const float*)d_in[9];
    const float* gate_w   = (const float*)d_in[10];
    const float* o_w      = (const float*)d_in[11];
    const float* ffn_gate = (const float*)d_in[12];
    const float* ffn_up   = (const float*)d_in[13];
    const float* ffn_down = (const float*)d_in[14];
    float* out = (float*)d_out;

    float *q, *k, *v, *gate, *beta;
    __half *xn16, *ao16, *g16, *u16, *qw16, *kw16, *vw16, *gw16, *ow16, *fg16, *fu16, *fd16;
    cudaGetSymbolAddress((void**)&q,    g_q);
    cudaGetSymbolAddress((void**)&k,    g_k);
    cudaGetSymbolAddress((void**)&v,    g_v);
    cudaGetSymbolAddress((void**)&gate, g_gate);
    cudaGetSymbolAddress((void**)&beta, g_beta);
    cudaGetSymbolAddress((void**)&xn16, h_xn);
    cudaGetSymbolAddress((void**)&ao16, h_ao);
    cudaGetSymbolAddress((void**)&g16,  h_g);
    cudaGetSymbolAddress((void**)&u16,  h_u);
    cudaGetSymbolAddress((void**)&qw16, h_qw);
    cudaGetSymbolAddress((void**)&kw16, h_kw);
    cudaGetSymbolAddress((void**)&vw16, h_vw);
    cudaGetSymbolAddress((void**)&gw16, h_gw);
    cudaGetSymbolAddress((void**)&ow16, h_ow);
    cudaGetSymbolAddress((void**)&fg16, h_fg);
    cudaGetSymbolAddress((void**)&fu16, h_fu);
    cudaGetSymbolAddress((void**)&fd16, h_fd);

    cudaFuncSetAttribute(gemm_qkvg, cudaFuncAttributeMaxDynamicSharedMemorySize, GEMM_SMEM);
    cudaFuncSetAttribute(gemm_gu,   cudaFuncAttributeMaxDynamicSharedMemorySize, GEMM_SMEM);
    cudaFuncSetAttribute(gemm_res,  cudaFuncAttributeMaxDynamicSharedMemorySize, GEMM_SMEM);

    const int CC2 = Cc * Cc;          // 1M
    const int CF  = FFN * Cc;         // 4M

    // 0. weight conversions fp32 -> fp16
    f2h_kernel<<<CC2/1024, 256>>>(q_w,      qw16, CC2);
    f2h_kernel<<<CC2/1024, 256>>>(k_w,      kw16, CC2);
    f2h_kernel<<<CC2/1024, 256>>>(v_w,      vw16, CC2);
    f2h_kernel<<<CC2/1024, 256>>>(gate_w,   gw16, CC2);
    f2h_kernel<<<CC2/1024, 256>>>(o_w,      ow16, CC2);
    f2h_kernel<<<CF/1024,  256>>>(ffn_gate, fg16, CF);
    f2h_kernel<<<CF/1024,  256>>>(ffn_up,   fu16, CF);
    f2h_kernel<<<CF/1024,  256>>>(ffn_down, fd16, CF);

    dim3 blk(256);
    dim3 grid_qkvg(Cc / 128, ROWS / 128, 4);
    dim3 grid_c(Cc / 128, ROWS / 128);
    dim3 grid_gu(FFN / 128, ROWS / 128, 2);

    // 1. xn1 = rmsnorm(x, norm1_w) -> fp16
    rmsnorm_kernel<<<ROWS, 256>>>(x, norm1_w, xn16);

    // 2. fused q/k/v/gate projections (+ sigmoid on gate)
    gemm_qkvg<<<grid_qkvg, blk, GEMM_SMEM>>>(xn16, qw16, kw16, vw16, gw16, q, k, v, gate);
    beta_kernel<<<ROWS, 512>>>(xn16, beta_w, beta_b, beta);

    // 3. l2 normalize q, k per head (one launch)
    l2norm_kernel<<<dim3((ROWS * Hh) / 8, 2), 256>>>(q, k);

    // 4. chunk-staged sequential delta-rule scan; writes ao = half(gate*o)
    scan_kernel<<<Bb * Hh, 128>>>(q, k, v, beta, gate, ao16);

    // 5. x1 = x + ao @ o_w.T -> out
    gemm_res<<<grid_c, blk, GEMM_SMEM>>>(ao16, ow16, x, out, Cc, Cc);

    // 6. xn2 = rmsnorm(x1, norm2_w) -> fp16
    rmsnorm_kernel<<<ROWS, 256>>>(out, norm2_w, xn16);

    // 7. FFN: g = silu(xn2@Wg.T), u = xn2@Wu.T (half); g *= u; out += g @ Wd.T
    gemm_gu<<<grid_gu, blk, GEMM_SMEM>>>(xn16, fg16, fu16, g16, u16);
    gu_kernel<<<(ROWS * FFN) / 512, 256>>>((__half2*)g16, (const __half2*)u16);
    gemm_res<<<grid_c, blk, GEMM_SMEM>>>(g16, fd16, out, out, Cc, FFN);
}